// round 10
// baseline (speedup 1.0000x reference)
#include <cuda_runtime.h>
#include <cuda_bf16.h>
#include <cstdint>

// SimCLR NT-Xent loss — e4m3 mma.sync m16n8k32 (sm_100 plain target).
// K0: normalize rows -> fp32 feats (exact pos term) + e4m3 feats (GEMM).
// K1: persistent CTAs (2/SM) over symmetric 128x128 tile pairs (I<=J).
//     S = A.B^T via ldmatrix(b16-pairs-of-fp8) + mma.sync m16n8k32 e4m3
//     (fp32 acc in regs); epilogue e = exp2(14.427 s - 14.427), mask,
//     scatter row (I) + col (J) sums with atomics. fp8 error only perturbs
//     the logsumexp denominator (softmax average -> bias ~2e-4 on rowsum).
// K2: loss = mean(-10*pos + 10 + log(rowsum)), pos dot exact in fp32.

#define N2 8192
#define HALF 4096
#define D 128
#define NT 64
#define NPAIRS 2080
#define NSM 148
#define NBLK (2 * NSM)
#define INV_T 10.0f
#define SHIFT 10.0f
#define C_EX2 14.426950408889634f   /* 10 * log2(e) */

__device__ __align__(16) float g_feats[N2 * D];
__device__ __align__(16) uint8_t g_e4[N2 * D];
__device__ float g_rowsum[N2];

#define SW128(o) ((o) ^ (((o) >> 3) & 0x70))

// ---------------- SMEM layout ----------------
// tile = 128 rows x 128 fp8 = 16KB: [16 8-row blocks][8 rows x 128B], SW128.
#define T_A 0
#define T_B 16384             /* two bufs of 16KB at +buf*16384 */
#define T_ROWP 49152          /* float rowpart[8][64] = 2048 B */
#define T_COLP 51200          /* float colpart[8][32] = 1024 B */
#define SMEM_TOTAL 52224      /* x2 CTAs = 102KB/SM */

__device__ __forceinline__ uint32_t smem_u32(const void* p) {
    uint32_t a;
    asm("{ .reg .u64 t; cvta.to.shared.u64 t, %1; cvt.u32.u64 %0, t; }" : "=r"(a) : "l"(p));
    return a;
}

// swizzled byte offset of (row r, 16B-unit g in 0..7) inside a 128x128 fp8 tile
__device__ __forceinline__ uint32_t tile_off(int r, int g) {
    uint32_t off = (uint32_t)((r >> 3) * 1024 + (r & 7) * 128 + g * 16);
    return SW128(off);
}

__device__ __forceinline__ void stage_async(const uint8_t* __restrict__ src,
                                            int rowbase, uint32_t dst, int tid) {
    const char* s = (const char*)(src + (size_t)rowbase * D);
    #pragma unroll
    for (int it = 0; it < 4; ++it) {
        int q = it * 256 + tid;           // 1024 16B chunks
        int r = q >> 3, g = q & 7;
        uint32_t d = dst + tile_off(r, g);
        asm volatile("cp.async.cg.shared.global [%0], [%1], 16;"
                     :: "r"(d), "l"(s + r * 128 + g * 16) : "memory");
    }
}

#define CP_COMMIT() asm volatile("cp.async.commit_group;" ::: "memory")
#define CP_WAIT0()  asm volatile("cp.async.wait_group 0;" ::: "memory")

#define LDSM_X4(R, A)                                                          \
    asm volatile("ldmatrix.sync.aligned.m8n8.x4.shared.b16 {%0,%1,%2,%3}, [%4];" \
        : "=r"((R)[0]), "=r"((R)[1]), "=r"((R)[2]), "=r"((R)[3]) : "r"(A))

// m16n8k32 e4m3: A = 4 regs (16 fp8/lane), B = 2 regs, C fp32 4 regs
__device__ __forceinline__ void mma16832(float* c, const uint32_t* a,
                                         uint32_t b0, uint32_t b1) {
    asm volatile("mma.sync.aligned.m16n8k32.row.col.f32.e4m3.e4m3.f32 "
        "{%0,%1,%2,%3}, {%4,%5,%6,%7}, {%8,%9}, {%0,%1,%2,%3};"
        : "+f"(c[0]), "+f"(c[1]), "+f"(c[2]), "+f"(c[3])
        : "r"(a[0]), "r"(a[1]), "r"(a[2]), "r"(a[3]), "r"(b0), "r"(b1));
}

__device__ __forceinline__ float ex2f(float x) {
    float r;
    asm("ex2.approx.ftz.f32 %0, %1;" : "=f"(r) : "f"(x));
    return r;
}

__device__ __forceinline__ uint32_t pack_e4m3x4(float a, float b, float c, float d) {
    uint16_t lo, hi;
    asm("cvt.rn.satfinite.e4m3x2.f32 %0, %2, %1;" : "=h"(lo) : "f"(a), "f"(b));
    asm("cvt.rn.satfinite.e4m3x2.f32 %0, %2, %1;" : "=h"(hi) : "f"(c), "f"(d));
    return (uint32_t)lo | ((uint32_t)hi << 16);
}

// ---------------------------------------------------------------- K0
__global__ void k0_normalize(const float* __restrict__ z1,
                             const float* __restrict__ z2,
                             float* __restrict__ out) {
    int w = threadIdx.x >> 5, lane = threadIdx.x & 31;
    int row = blockIdx.x * 8 + w;
    const float* src = (row < HALF) ? (z1 + (size_t)row * D)
                                    : (z2 + (size_t)(row - HALF) * D);
    float4 f = ((const float4*)src)[lane];
    float ss = f.x * f.x + f.y * f.y + f.z * f.z + f.w * f.w;
    #pragma unroll
    for (int o = 16; o; o >>= 1) ss += __shfl_xor_sync(0xffffffffu, ss, o);
    float inv = rsqrtf(fmaxf(ss, 1e-24f));
    f.x *= inv; f.y *= inv; f.z *= inv; f.w *= inv;
    ((float4*)(g_feats + (size_t)row * D))[lane] = f;
    ((uint32_t*)(g_e4 + (size_t)row * D))[lane] = pack_e4m3x4(f.x, f.y, f.z, f.w);
    if (lane == 0) g_rowsum[row] = 0.0f;
    if (blockIdx.x == 0 && threadIdx.x == 0) out[0] = 0.0f;
}

// ---------------------------------------------------------------- K1
__device__ __forceinline__ void decode_tile(int t, int& I, int& J) {
    int k = t, i = 0;
    while (k >= NT - i) { k -= NT - i; ++i; }
    I = i; J = i + k;
}

__global__ void __launch_bounds__(256, 2) k1_mma() {
    extern __shared__ char smem[];
    uint32_t sb = smem_u32(smem);
    float* rowpart = (float*)(smem + T_ROWP);   // [8][64]
    float* colpart = (float*)(smem + T_COLP);   // [8][32]
    int tid = threadIdx.x, lane = tid & 31, w = tid >> 5;
    int wy = w >> 2, wx = w & 3;               // warp tile: rows wy*64, cols wx*32

    int start = (int)((long long)blockIdx.x * NPAIRS / NBLK);
    int end   = (int)((long long)(blockIdx.x + 1) * NPAIRS / NBLK);
    if (start >= end) return;

    int I, J;
    decode_tile(start, I, J);
    int buf = 0;
    stage_async(g_e4, I * 128, sb + T_A, tid);
    stage_async(g_e4, J * 128, sb + T_B, tid);
    CP_COMMIT(); CP_WAIT0();
    __syncthreads();

    for (int t = start; t < end; ++t) {
        bool havenext = (t + 1 < end);
        int nI = I, nJ = J;
        if (havenext) decode_tile(t + 1, nI, nJ);
        bool pf = havenext && (nI == I);
        if (pf) {   // prefetch next B into other buffer, overlapped with compute
            stage_async(g_e4, nJ * 128, sb + T_B + (buf ^ 1) * 16384, tid);
            CP_COMMIT();
        }

        // ---------------- compute: 4 k32-steps ----------------
        float acc[4][4][4];
        #pragma unroll
        for (int mt = 0; mt < 4; ++mt)
            #pragma unroll
            for (int nt = 0; nt < 4; ++nt)
                #pragma unroll
                for (int r = 0; r < 4; ++r) acc[mt][nt][r] = 0.0f;

        int rA = lane & 15;
        int rB = ((lane >> 4) << 3) + (lane & 7);
        uint32_t Ab = sb + T_A;
        uint32_t Bb = sb + T_B + buf * 16384;
        #pragma unroll
        for (int k0 = 0; k0 < 4; ++k0) {
            int gA = k0 * 2 + (lane >> 4);          // 16B unit within row
            int gB = k0 * 2 + ((lane >> 3) & 1);
            uint32_t a[4][4], b[2][4];
            #pragma unroll
            for (int mt = 0; mt < 4; ++mt)
                LDSM_X4(a[mt], Ab + tile_off(wy * 64 + mt * 16 + rA, gA));
            #pragma unroll
            for (int np = 0; np < 2; ++np)
                LDSM_X4(b[np], Bb + tile_off(wx * 32 + np * 16 + rB, gB));
            // a = {r0-7/k0-15, r8-15/k0-15, r0-7/k16-31, r8-15/k16-31} = a0..a3
            // b[np] = {c0-7/k0-15, c0-7/k16-31, c8-15/k0-15, c8-15/k16-31}
            #pragma unroll
            for (int mt = 0; mt < 4; ++mt)
                #pragma unroll
                for (int nt = 0; nt < 4; ++nt)
                    mma16832(acc[mt][nt], a[mt],
                             b[nt >> 1][(nt & 1) * 2], b[nt >> 1][(nt & 1) * 2 + 1]);
        }

        // I-run ends next iteration: issue the A(+B) reload NOW so the L2
        // fetch overlaps the epilogue below (compute has finished reading A).
        bool reload = havenext && !pf;
        if (reload) {
            __syncthreads();   // all warps done with ldsm reads of A/B
            stage_async(g_e4, nI * 128, sb + T_A, tid);
            stage_async(g_e4, nJ * 128, sb + T_B + buf * 16384, tid);
            CP_COMMIT();
        }

        // ---------------- epilogue ----------------
        // mask: both diag (I==J) and positive-pair (J-I==32) reduce to row_loc==col_loc
        bool maskT = (I == J) || (J - I == 32);
        float rs[4][2], cs[4][2];
        #pragma unroll
        for (int i = 0; i < 4; ++i) { rs[i][0] = rs[i][1] = cs[i][0] = cs[i][1] = 0.f; }
        int rl0 = wy * 64 + (lane >> 2);          // + mt*16 (+8)
        int cl0 = wx * 32 + (lane & 3) * 2;       // + nt*8 (+1)
        #pragma unroll
        for (int mt = 0; mt < 4; ++mt) {
            int R0 = rl0 + mt * 16, R1 = R0 + 8;
            #pragma unroll
            for (int nt = 0; nt < 4; ++nt) {
                int C0 = cl0 + nt * 8, C1 = C0 + 1;
                float* c = acc[mt][nt];
                float e0 = ex2f(fmaf(c[0], C_EX2, -C_EX2));
                float e1 = ex2f(fmaf(c[1], C_EX2, -C_EX2));
                float e2 = ex2f(fmaf(c[2], C_EX2, -C_EX2));
                float e3 = ex2f(fmaf(c[3], C_EX2, -C_EX2));
                if (maskT) {
                    if (R0 == C0) e0 = 0.f;
                    if (R0 == C1) e1 = 0.f;
                    if (R1 == C0) e2 = 0.f;
                    if (R1 == C1) e3 = 0.f;
                }
                rs[mt][0] += e0 + e1; rs[mt][1] += e2 + e3;
                cs[nt][0] += e0 + e2; cs[nt][1] += e1 + e3;
            }
        }
        // row partials: reduce across the 4 lanes of each row-quad
        #pragma unroll
        for (int mt = 0; mt < 4; ++mt) {
            #pragma unroll
            for (int h = 0; h < 2; ++h) {
                float v = rs[mt][h];
                v += __shfl_xor_sync(0xffffffffu, v, 1);
                v += __shfl_xor_sync(0xffffffffu, v, 2);
                if ((lane & 3) == 0)
                    rowpart[w * 64 + mt * 16 + (lane >> 2) + h * 8] = v;
            }
        }
        // col partials: reduce across the 8 lanes sharing a column set
        #pragma unroll
        for (int nt = 0; nt < 4; ++nt) {
            #pragma unroll
            for (int h = 0; h < 2; ++h) {
                float v = cs[nt][h];
                v += __shfl_xor_sync(0xffffffffu, v, 4);
                v += __shfl_xor_sync(0xffffffffu, v, 8);
                v += __shfl_xor_sync(0xffffffffu, v, 16);
                if (lane < 4)
                    colpart[w * 32 + nt * 8 + lane * 2 + h] = v;
            }
        }
        __syncthreads();
        if (tid < 128) {
            int i = tid;
            int h4 = (i >> 6) * 4, il = i & 63;
            float rtot = rowpart[(h4 + 0) * 64 + il] + rowpart[(h4 + 1) * 64 + il]
                       + rowpart[(h4 + 2) * 64 + il] + rowpart[(h4 + 3) * 64 + il];
            atomicAdd(&g_rowsum[I * 128 + i], rtot);
            int jx = i >> 5, jl = i & 31;
            float ctot = colpart[jx * 32 + jl] + colpart[(4 + jx) * 32 + jl];
            if (I != J) atomicAdd(&g_rowsum[J * 128 + i], ctot);
        }
        __syncthreads();

        // ---------------- advance ----------------
        if (havenext) {
            CP_WAIT0();
            __syncthreads();
            if (pf) buf ^= 1;
            I = nI; J = nJ;
        }
    }
}

// ---------------------------------------------------------------- K2
__global__ void k2_final(float* __restrict__ out) {
    int row = (blockIdx.x * blockDim.x + threadIdx.x) >> 5;
    int lane = threadIdx.x & 31;
    const float4* a = (const float4*)(g_feats + (size_t)row * D);
    int p = (row + HALF) & (N2 - 1);
    const float4* b = (const float4*)(g_feats + (size_t)p * D);
    float4 x = a[lane], y = b[lane];
    float dot = x.x * y.x + x.y * y.y + x.z * y.z + x.w * y.w;
    #pragma unroll
    for (int o = 16; o; o >>= 1) dot += __shfl_xor_sync(0xffffffffu, dot, o);

    __shared__ float bs[8];
    if (lane == 0) {
        float lossv = (-dot * INV_T + SHIFT + logf(g_rowsum[row])) * (1.0f / N2);
        bs[threadIdx.x >> 5] = lossv;
    }
    __syncthreads();
    if (threadIdx.x == 0) {
        float s = 0.0f;
        #pragma unroll
        for (int i = 0; i < 8; ++i) s += bs[i];
        atomicAdd(out, s);
    }
}

// ---------------------------------------------------------------- launch
extern "C" void kernel_launch(void* const* d_in, const int* in_sizes, int n_in,
                              void* d_out, int out_size) {
    const float* z1 = (const float*)d_in[0];
    const float* z2 = (const float*)d_in[1];
    float* out = (float*)d_out;

    cudaFuncSetAttribute(k1_mma, cudaFuncAttributeMaxDynamicSharedMemorySize, SMEM_TOTAL);

    k0_normalize<<<N2 / 8, 256>>>(z1, z2, out);
    k1_mma<<<NBLK, 256, SMEM_TOTAL>>>();
    k2_final<<<N2 / 8, 256>>>(out);
}

// round 12
// speedup vs baseline: 1.0289x; 1.0289x over previous
#include <cuda_runtime.h>
#include <cuda_bf16.h>
#include <cuda_fp16.h>
#include <cstdint>

// SimCLR NT-Xent loss — bf16 mma.sync + f16x2 exp epilogue (sm_100 plain).
// K0: normalize rows -> fp32 feats (exact pos term) + bf16 feats (GEMM).
// K1: persistent CTAs (2/SM) over symmetric 128x128 tile pairs (I<=J).
//     S = A.B^T via ldmatrix + mma.sync m16n8k16 bf16 (fp32 acc in regs).
//     Epilogue: e' = 2^(14.43 s - 0.43) = exp(10s-10)*2^14 via ex2.approx.f16x2
//     (biased so terms sit in f16 normal range), mask, shfl-reduce, and
//     scatter row/col sums DIRECTLY with RED.F32 (no smem, no barriers).
// K2: loss = mean(-10*pos + 10 + log(rowsum') - 14 ln2), pos dot exact fp32.

#define N2 8192
#define HALF 4096
#define D 128
#define NT 64
#define NPAIRS 2080
#define NSM 148
#define NBLK (2 * NSM)
#define INV_T 10.0f
#define SHIFT 10.0f
#define C_EX2 14.426950408889634f   /* 10 * log2(e) */
#define BIASC (14.0f - C_EX2)       /* exponent bias: terms *= 2^14 */
#define LN2_14 9.704060527839234f   /* 14 * ln 2 */

__device__ __align__(16) float g_feats[N2 * D];
__device__ __align__(16) __nv_bfloat16 g_bf[N2 * D];
__device__ float g_rowsum[N2];

#define SW128(o) ((o) ^ (((o) >> 3) & 0x70))

// ---------------- SMEM layout ----------------
// tile = 128 rows x 128 bf16 = 32KB, two 16KB atom-columns, SW128 swizzled.
#define T_A 0
#define T_B 32768             /* two bufs of 32KB at +buf*32768 */
#define SMEM_TOTAL 98304      /* x2 CTAs = 192KB/SM */

__device__ __forceinline__ uint32_t smem_u32(const void* p) {
    uint32_t a;
    asm("{ .reg .u64 t; cvta.to.shared.u64 t, %1; cvt.u32.u64 %0, t; }" : "=r"(a) : "l"(p));
    return a;
}

// swizzled byte offset of (row r, 16B-unit g in 0..15) inside a 128x128 bf16 tile
__device__ __forceinline__ uint32_t tile_off(int r, int g) {
    uint32_t off = (uint32_t)(((r >> 3) + (g >> 3) * 16) * 1024 + (r & 7) * 128 + (g & 7) * 16);
    return SW128(off);
}

__device__ __forceinline__ void stage_async(const __nv_bfloat16* __restrict__ src,
                                            int rowbase, uint32_t dst, int tid) {
    const char* s = (const char*)(src + (size_t)rowbase * D);
    #pragma unroll
    for (int it = 0; it < 8; ++it) {
        int q = it * 256 + tid;           // 2048 16B chunks
        int r = q >> 4, g = q & 15;
        uint32_t d = dst + tile_off(r, g);
        asm volatile("cp.async.cg.shared.global [%0], [%1], 16;"
                     :: "r"(d), "l"(s + r * 256 + g * 16) : "memory");
    }
}

#define CP_COMMIT() asm volatile("cp.async.commit_group;" ::: "memory")
#define CP_WAIT0()  asm volatile("cp.async.wait_group 0;" ::: "memory")

#define LDSM_X4(R, A)                                                          \
    asm volatile("ldmatrix.sync.aligned.m8n8.x4.shared.b16 {%0,%1,%2,%3}, [%4];" \
        : "=r"((R)[0]), "=r"((R)[1]), "=r"((R)[2]), "=r"((R)[3]) : "r"(A))

__device__ __forceinline__ void mma16816(float* c, const uint32_t* a,
                                         uint32_t b0, uint32_t b1) {
    asm volatile("mma.sync.aligned.m16n8k16.row.col.f32.bf16.bf16.f32 "
        "{%0,%1,%2,%3}, {%4,%5,%6,%7}, {%8,%9}, {%0,%1,%2,%3};"
        : "+f"(c[0]), "+f"(c[1]), "+f"(c[2]), "+f"(c[3])
        : "r"(a[0]), "r"(a[1]), "r"(a[2]), "r"(a[3]), "r"(b0), "r"(b1));
}

// packed f16x2 exp2
__device__ __forceinline__ uint32_t ex2_h2(uint32_t x) {
    uint32_t r;
    asm("ex2.approx.f16x2 %0, %1;" : "=r"(r) : "r"(x));
    return r;
}

// ---------------------------------------------------------------- K0
__global__ void k0_normalize(const float* __restrict__ z1,
                             const float* __restrict__ z2,
                             float* __restrict__ out) {
    int w = threadIdx.x >> 5, lane = threadIdx.x & 31;
    int row = blockIdx.x * 8 + w;
    const float* src = (row < HALF) ? (z1 + (size_t)row * D)
                                    : (z2 + (size_t)(row - HALF) * D);
    float4 f = ((const float4*)src)[lane];
    float ss = f.x * f.x + f.y * f.y + f.z * f.z + f.w * f.w;
    #pragma unroll
    for (int o = 16; o; o >>= 1) ss += __shfl_xor_sync(0xffffffffu, ss, o);
    float inv = rsqrtf(fmaxf(ss, 1e-24f));
    f.x *= inv; f.y *= inv; f.z *= inv; f.w *= inv;
    ((float4*)(g_feats + (size_t)row * D))[lane] = f;

    __nv_bfloat162 b0 = __floats2bfloat162_rn(f.x, f.y);
    __nv_bfloat162 b1 = __floats2bfloat162_rn(f.z, f.w);
    ((uint2*)(g_bf + (size_t)row * D))[lane] =
        make_uint2(*(uint32_t*)&b0, *(uint32_t*)&b1);
    if (lane == 0) g_rowsum[row] = 0.0f;
    if (blockIdx.x == 0 && threadIdx.x == 0) out[0] = 0.0f;
}

// ---------------------------------------------------------------- K1
__device__ __forceinline__ void decode_tile(int t, int& I, int& J) {
    int k = t, i = 0;
    while (k >= NT - i) { k -= NT - i; ++i; }
    I = i; J = i + k;
}

__global__ void __launch_bounds__(256, 2) k1_mma() {
    extern __shared__ char smem[];
    uint32_t sb = smem_u32(smem);
    int tid = threadIdx.x, lane = tid & 31, w = tid >> 5;
    int wy = w >> 2, wx = w & 3;               // warp tile: rows wy*64, cols wx*32

    int start = (int)((long long)blockIdx.x * NPAIRS / NBLK);
    int end   = (int)((long long)(blockIdx.x + 1) * NPAIRS / NBLK);
    if (start >= end) return;

    int I, J;
    decode_tile(start, I, J);
    int buf = 0;
    stage_async(g_bf, I * 128, sb + T_A, tid);
    stage_async(g_bf, J * 128, sb + T_B, tid);
    CP_COMMIT(); CP_WAIT0();
    __syncthreads();

    for (int t = start; t < end; ++t) {
        bool havenext = (t + 1 < end);
        int nI = I, nJ = J;
        if (havenext) decode_tile(t + 1, nI, nJ);
        bool pf = havenext && (nI == I);
        if (pf) {   // prefetch next B into other buffer, overlapped with compute
            stage_async(g_bf, nJ * 128, sb + T_B + (buf ^ 1) * 32768, tid);
            CP_COMMIT();
        }

        // ---------------- compute: 8 k16-steps ----------------
        float acc[4][4][4];
        #pragma unroll
        for (int mt = 0; mt < 4; ++mt)
            #pragma unroll
            for (int nt = 0; nt < 4; ++nt)
                #pragma unroll
                for (int r = 0; r < 4; ++r) acc[mt][nt][r] = 0.0f;

        int rA = lane & 15;
        int rB = ((lane >> 4) << 3) + (lane & 7);
        uint32_t Ab = sb + T_A;
        uint32_t Bb = sb + T_B + buf * 32768;
        #pragma unroll
        for (int k0 = 0; k0 < 8; ++k0) {
            int gA = k0 * 2 + (lane >> 4);
            int gB = k0 * 2 + ((lane >> 3) & 1);
            uint32_t a[4][4], b[2][4];
            #pragma unroll
            for (int mt = 0; mt < 4; ++mt)
                LDSM_X4(a[mt], Ab + tile_off(wy * 64 + mt * 16 + rA, gA));
            #pragma unroll
            for (int np = 0; np < 2; ++np)
                LDSM_X4(b[np], Bb + tile_off(wx * 32 + np * 16 + rB, gB));
            #pragma unroll
            for (int mt = 0; mt < 4; ++mt)
                #pragma unroll
                for (int nt = 0; nt < 4; ++nt)
                    mma16816(acc[mt][nt], a[mt],
                             b[nt >> 1][(nt & 1) * 2], b[nt >> 1][(nt & 1) * 2 + 1]);
        }

        // I-run ends next iteration: issue the A(+B) reload NOW so the L2
        // fetch overlaps the epilogue (compute has finished reading A).
        bool reload = havenext && !pf;
        if (reload) {
            __syncthreads();   // all warps done with ldsm reads of A/B
            stage_async(g_bf, nI * 128, sb + T_A, tid);
            stage_async(g_bf, nJ * 128, sb + T_B + buf * 32768, tid);
            CP_COMMIT();
        }

        // ---------------- epilogue (no smem, no barriers) ----------------
        // e' = 2^(14.43 s - 0.43) = exp(10s-10) * 2^14  (bias keeps f16 normal)
        // mask: diag (I==J) and positive-pair (J-I==32) both = row_loc==col_loc
        bool maskT = (I == J) || (J - I == 32);
        float rs[4][2], cs[4][2];
        #pragma unroll
        for (int i = 0; i < 4; ++i) { rs[i][0] = rs[i][1] = cs[i][0] = cs[i][1] = 0.f; }
        int rl0 = wy * 64 + (lane >> 2);          // + mt*16 (+8)
        int cl0 = wx * 32 + (lane & 3) * 2;       // + nt*8 (+1)
        #pragma unroll
        for (int mt = 0; mt < 4; ++mt) {
            int R0 = rl0 + mt * 16, R1 = R0 + 8;
            #pragma unroll
            for (int nt = 0; nt < 4; ++nt) {
                int C0 = cl0 + nt * 8, C1 = C0 + 1;
                float* c = acc[mt][nt];
                float a0 = fmaf(c[0], C_EX2, BIASC);
                float a1 = fmaf(c[1], C_EX2, BIASC);
                float a2 = fmaf(c[2], C_EX2, BIASC);
                float a3 = fmaf(c[3], C_EX2, BIASC);
                if (maskT) {                     // -60 -> 2^-60 -> 0 in f16
                    if (R0 == C0) a0 = -60.f;
                    if (R0 == C1) a1 = -60.f;
                    if (R1 == C0) a2 = -60.f;
                    if (R1 == C1) a3 = -60.f;
                }
                __half2 h01 = __floats2half2_rn(a0, a1);
                __half2 h23 = __floats2half2_rn(a2, a3);
                uint32_t e01u = ex2_h2(*(uint32_t*)&h01);
                uint32_t e23u = ex2_h2(*(uint32_t*)&h23);
                float2 e01 = __half22float2(*(__half2*)&e01u);
                float2 e23 = __half22float2(*(__half2*)&e23u);
                rs[mt][0] += e01.x + e01.y;
                rs[mt][1] += e23.x + e23.y;
                cs[nt][0] += e01.x + e23.x;
                cs[nt][1] += e01.y + e23.y;
            }
        }
        // row sums: reduce over the 4 lanes of each row-quad, RED direct
        #pragma unroll
        for (int mt = 0; mt < 4; ++mt) {
            #pragma unroll
            for (int h = 0; h < 2; ++h) {
                float v = rs[mt][h];
                v += __shfl_xor_sync(0xffffffffu, v, 1);
                v += __shfl_xor_sync(0xffffffffu, v, 2);
                if ((lane & 3) == 0)
                    atomicAdd(&g_rowsum[I * 128 + wy * 64 + mt * 16 + (lane >> 2) + h * 8], v);
            }
        }
        // col sums: reduce over the 8 lanes sharing a column set, RED direct
        if (I != J) {
            #pragma unroll
            for (int nt = 0; nt < 4; ++nt) {
                #pragma unroll
                for (int h = 0; h < 2; ++h) {
                    float v = cs[nt][h];
                    v += __shfl_xor_sync(0xffffffffu, v, 4);
                    v += __shfl_xor_sync(0xffffffffu, v, 8);
                    v += __shfl_xor_sync(0xffffffffu, v, 16);
                    if (lane < 4)
                        atomicAdd(&g_rowsum[J * 128 + wx * 32 + nt * 8 + lane * 2 + h], v);
                }
            }
        }

        // ---------------- advance ----------------
        if (havenext) {
            CP_WAIT0();
            __syncthreads();
            if (pf) buf ^= 1;
            I = nI; J = nJ;
        }
    }
}

// ---------------------------------------------------------------- K2
__global__ void k2_final(float* __restrict__ out) {
    int row = (blockIdx.x * blockDim.x + threadIdx.x) >> 5;
    int lane = threadIdx.x & 31;
    const float4* a = (const float4*)(g_feats + (size_t)row * D);
    int p = (row + HALF) & (N2 - 1);
    const float4* b = (const float4*)(g_feats + (size_t)p * D);
    float4 x = a[lane], y = b[lane];
    float dot = x.x * y.x + x.y * y.y + x.z * y.z + x.w * y.w;
    #pragma unroll
    for (int o = 16; o; o >>= 1) dot += __shfl_xor_sync(0xffffffffu, dot, o);

    __shared__ float bs[8];
    if (lane == 0) {
        // rowsum is biased by 2^14: subtract 14 ln2
        float lossv = (-dot * INV_T + SHIFT + logf(g_rowsum[row]) - LN2_14) * (1.0f / N2);
        bs[threadIdx.x >> 5] = lossv;
    }
    __syncthreads();
    if (threadIdx.x == 0) {
        float s = 0.0f;
        #pragma unroll
        for (int i = 0; i < 8; ++i) s += bs[i];
        atomicAdd(out, s);
    }
}

// ---------------------------------------------------------------- launch
extern "C" void kernel_launch(void* const* d_in, const int* in_sizes, int n_in,
                              void* d_out, int out_size) {
    const float* z1 = (const float*)d_in[0];
    const float* z2 = (const float*)d_in[1];
    float* out = (float*)d_out;

    cudaFuncSetAttribute(k1_mma, cudaFuncAttributeMaxDynamicSharedMemorySize, SMEM_TOTAL);

    k0_normalize<<<N2 / 8, 256>>>(z1, z2, out);
    k1_mma<<<NBLK, 256, SMEM_TOTAL>>>();
    k2_final<<<N2 / 8, 256>>>(out);
}